// round 3
// baseline (speedup 1.0000x reference)
#include <cuda_runtime.h>
#include <math.h>

#define NN 8192
#define KK 32
#define NT 64                       // 8192/128 tiles per dim
#define NOFF (NT*(NT-1)/2)          // 2016 strictly-upper tiles
#define NTILES (NOFF + NT)          // 2080 partial slots

typedef unsigned long long u64;

#define FMA2(d,a,b,c) asm("fma.rn.f32x2 %0, %1, %2, %3;" : "=l"(d) : "l"(a), "l"(b), "l"(c))
#define PK2(d,lo,hi)  asm("mov.b64 %0, {%1, %2};" : "=l"(d) : "f"(lo), "f"(hi))
#define UPK2(lo,hi,s) asm("mov.b64 {%0, %1}, %2;" : "=f"(lo), "=f"(hi) : "l"(s))

// ---- scratch (no allocations allowed) ----
__device__ float  d_Wpart[64*KK*KK];    // partial Xs @ expC per 128-chunk
__device__ float  d_Spart[64*KK];       // partial column sums of expC
__device__ float  d_W [KK*KK];
__device__ float  d_S [KK];
__device__ float  d_M [KK*KK];          // M = E^T E
__device__ float  d_Ya[KK*NN];          // 2a * M @ X
__device__ float  d_bv[NN];             // beta - a*q
__device__ double d_partSP[NTILES];
__device__ double d_partTA[NTILES];

// ---------- fused prep: softmax(X) chunk + exp(C) chunk + partial W,S ----------
__global__ void k_prep(const float* __restrict__ X, const float* __restrict__ C) {
    __shared__ float xs[KK][132];   // Xs[p][ii]
    __shared__ float ec[KK][132];   // expC[base+ii][k] -> ec[k][ii]
    int blk = blockIdx.x, tid = threadIdx.x;
    int base = blk * 128;

    if (tid < 128) {
        // softmax over K=32 rows for column base+tid (no max-shift: inputs ~N(0,1))
        int i = base + tid;
        float v[KK]; float s = 0.f;
#pragma unroll
        for (int p = 0; p < KK; p++) { v[p] = __expf(X[p*NN + i]); s += v[p]; }
        float inv = 1.f / s;
#pragma unroll
        for (int p = 0; p < KK; p++) xs[p][tid] = v[p] * inv;
    } else {
        // exp of one C row (32 consecutive floats)
        int r = tid - 128;
        const float4* cp = (const float4*)&C[(base + r)*KK];
#pragma unroll
        for (int c4 = 0; c4 < 8; c4++) {
            float4 v = cp[c4];
            ec[c4*4+0][r] = __expf(v.x);
            ec[c4*4+1][r] = __expf(v.y);
            ec[c4*4+2][r] = __expf(v.z);
            ec[c4*4+3][r] = __expf(v.w);
        }
    }
    __syncthreads();

    // partial column sums of expC
    if (tid < 32) {
        float s = 0.f;
#pragma unroll 8
        for (int r = 0; r < 128; r++) s += ec[tid][r];
        d_Spart[blk*32 + tid] = s;
    }

    // partial W = Xs_chunk @ expC_chunk  (32x32)
    int p = tid >> 3, k0 = (tid & 7) * 4;
    float a0 = 0.f, a1 = 0.f, a2 = 0.f, a3 = 0.f;
#pragma unroll 4
    for (int ii = 0; ii < 128; ii++) {
        float xv = xs[p][ii];
        a0 += xv * ec[k0+0][ii];
        a1 += xv * ec[k0+1][ii];
        a2 += xv * ec[k0+2][ii];
        a3 += xv * ec[k0+3][ii];
    }
    float* out = &d_Wpart[blk*1024 + p*32 + k0];
    out[0] = a0; out[1] = a1; out[2] = a2; out[3] = a3;
}

// ---------- reduce partials ----------
__global__ void k_wred() {
    int tid = threadIdx.x;
#pragma unroll
    for (int c = 0; c < 4; c++) {
        int e = tid*4 + c;
        float s = 0.f;
#pragma unroll 8
        for (int b = 0; b < 64; b++) s += d_Wpart[b*1024 + e];
        d_W[e] = s;
    }
    if (tid < 32) {
        float s = 0.f;
#pragma unroll 8
        for (int b = 0; b < 64; b++) s += d_Spart[b*32 + tid];
        d_S[tid] = s;
    }
}

// ---------- E = W / S ;  M = E^T E ----------
__global__ void k_M() {
    __shared__ float Es[KK*KK];
    int tid = threadIdx.x;
#pragma unroll
    for (int c = 0; c < 4; c++) {
        int e = tid*4 + c;
        Es[e] = d_W[e] / d_S[e & 31];
    }
    __syncthreads();
#pragma unroll
    for (int c = 0; c < 4; c++) {
        int e = tid*4 + c;
        int p = e >> 5, q = e & 31;
        float s = 0.f;
#pragma unroll
        for (int r = 0; r < KK; r++) s += Es[r*KK + p] * Es[r*KK + q];
        d_M[e] = s;
    }
}

// ---------- Ya = 2a*M*X, b = beta - a*q  (warp w handles p in [8w,8w+8)) ----------
__global__ void k_ya(const float* __restrict__ X, const float* __restrict__ beta,
                     const float* __restrict__ a_p) {
    __shared__ float Ms[KK][KK+1];
    __shared__ float qsm[4][32];
    int tid = threadIdx.x;
    int lane = tid & 31, w = tid >> 5;
    for (int idx = tid; idx < KK*KK; idx += 128)
        Ms[idx >> 5][idx & 31] = d_M[idx];
    __syncthreads();

    int i = blockIdx.x * 32 + lane;
    float a = a_p[0];
    float twoa = 2.f * a;
    float xv[KK];
#pragma unroll
    for (int q = 0; q < KK; q++) xv[q] = X[q*NN + i];

    float qp = 0.f;
#pragma unroll
    for (int pp = 0; pp < 8; pp++) {
        int p = w*8 + pp;
        float tp = 0.f;
#pragma unroll
        for (int q = 0; q < KK; q++) tp += Ms[p][q] * xv[q];
        d_Ya[p*NN + i] = twoa * tp;
        qp += xv[p] * tp;
    }
    qsm[w][lane] = qp;
    __syncthreads();
    if (w == 0) {
        float qf = qsm[0][lane] + qsm[1][lane] + qsm[2][lane] + qsm[3][lane];
        d_bv[i] = beta[i] - a * qf;
    }
}

__device__ __forceinline__ float softplusf(float x) {
    return fmaxf(x, 0.f) + __logf(1.f + __expf(-fabsf(x)));
}

// ---------- shared tile core: loads + theta accumulation ----------
struct TileCtx {
    u64 acc2[8][4];
    int tx, ty;
};

__device__ __forceinline__ void tile_theta(
    TileCtx& ctx, const float* __restrict__ X, int iBase, int jBase, int tid,
    float (&Xt)[KK][128], float (&Yt)[KK][128], float (&bI)[128], float (&bJ)[128])
{
#pragma unroll
    for (int c = 0; c < 4; c++) {
        int e = c*1024 + tid*4;
        int p = e >> 7, ii = e & 127;
        *(float4*)&Xt[p][ii] = *(const float4*)&X   [p*NN + iBase + ii];
        *(float4*)&Yt[p][ii] = *(const float4*)&d_Ya[p*NN + jBase + ii];
    }
    if (tid < 128) bI[tid] = d_bv[iBase + tid];
    else           bJ[tid - 128] = d_bv[jBase + tid - 128];
    __syncthreads();

    int tx = tid & 15, ty = tid >> 4;
    ctx.tx = tx; ctx.ty = ty;
    float bIr[8], bJc[8];
#pragma unroll
    for (int r = 0; r < 8; r++) bIr[r] = bI[ty*8 + r];
#pragma unroll
    for (int c = 0; c < 4; c++) { bJc[c] = bJ[tx*4 + c]; bJc[c+4] = bJ[64 + tx*4 + c]; }

#pragma unroll
    for (int r = 0; r < 8; r++)
#pragma unroll
        for (int cp = 0; cp < 4; cp++)
            PK2(ctx.acc2[r][cp], bIr[r] + bJc[2*cp], bIr[r] + bJc[2*cp + 1]);

#pragma unroll
    for (int k = 0; k < KK; k++) {
        float4 xa = *(float4*)&Xt[k][ty*8];
        float4 xb = *(float4*)&Xt[k][ty*8 + 4];
        const u64* yp0 = (const u64*)&Yt[k][tx*4];
        const u64* yp1 = (const u64*)&Yt[k][64 + tx*4];
        u64 y2[4] = {yp0[0], yp0[1], yp1[0], yp1[1]};
        float xf[8] = {xa.x, xa.y, xa.z, xa.w, xb.x, xb.y, xb.z, xb.w};
#pragma unroll
        for (int r = 0; r < 8; r++) {
            u64 xx;
            PK2(xx, xf[r], xf[r]);
#pragma unroll
            for (int cp = 0; cp < 4; cp++)
                FMA2(ctx.acc2[r][cp], xx, y2[cp], ctx.acc2[r][cp]);
        }
    }
}

__device__ __forceinline__ void block_reduce_store(float sSP, float sTA, int tid, int slot,
                                                   float (&wSP)[8], float (&wTA)[8]) {
#pragma unroll
    for (int o = 16; o > 0; o >>= 1) {
        sSP += __shfl_xor_sync(0xffffffffu, sSP, o);
        sTA += __shfl_xor_sync(0xffffffffu, sTA, o);
    }
    int wid = tid >> 5, lane = tid & 31;
    if (lane == 0) { wSP[wid] = sSP; wTA[wid] = sTA; }
    __syncthreads();
    if (tid == 0) {
        float s1 = 0.f, s2 = 0.f;
#pragma unroll
        for (int w = 0; w < 8; w++) { s1 += wSP[w]; s2 += wTA[w]; }
        d_partSP[slot] = (double)s1;
        d_partTA[slot] = (double)s2;
    }
}

// ---------- diagonal tiles (I==J), 64 blocks ----------
__global__ void __launch_bounds__(256, 2)
k_pairs_diag(const float* __restrict__ X, const float* __restrict__ A) {
    __shared__ float Xt[KK][128], Yt[KK][128], bI[128], bJ[128];
    __shared__ float wSP[8], wTA[8];
    int I = blockIdx.x;
    int iBase = I * 128, jBase = iBase;
    int tid = threadIdx.x;

    TileCtx ctx;
    tile_theta(ctx, X, iBase, jBase, tid, Xt, Yt, bI, bJ);
    int tx = ctx.tx, ty = ctx.ty;

    float sSP = 0.f, sTA = 0.f;
#pragma unroll
    for (int r = 0; r < 8; r++) {
        int gi = iBase + ty*8 + r;
        float4 a0 = __ldcs((const float4*)&A[gi*NN + jBase + tx*4]);
        float4 a1 = __ldcs((const float4*)&A[gi*NN + jBase + 64 + tx*4]);
        float av[8] = {a0.x, a0.y, a0.z, a0.w, a1.x, a1.y, a1.z, a1.w};
#pragma unroll
        for (int c = 0; c < 8; c++) {
            int gj = jBase + ((c < 4) ? (tx*4 + c) : (64 + tx*4 + (c - 4)));
            float t0, t1;
            UPK2(t0, t1, ctx.acc2[r][c >> 1]);
            float th = (c & 1) ? t1 : t0;
            if (gi < gj) {
                sSP += 2.f * softplusf(th);
                sTA += th * av[c];
            } else if (gi == gj) {
                sTA += th * av[c];
            }
        }
    }
#pragma unroll
    for (int c = 0; c < 8; c++) {
        int gj = jBase + ((c < 4) ? (tx*4 + c) : (64 + tx*4 + (c - 4)));
        float4 b0 = __ldcs((const float4*)&A[gj*NN + iBase + ty*8]);
        float4 b1 = __ldcs((const float4*)&A[gj*NN + iBase + ty*8 + 4]);
        float atv[8] = {b0.x, b0.y, b0.z, b0.w, b1.x, b1.y, b1.z, b1.w};
#pragma unroll
        for (int r = 0; r < 8; r++) {
            int gi = iBase + ty*8 + r;
            float t0, t1;
            UPK2(t0, t1, ctx.acc2[r][c >> 1]);
            float th = (c & 1) ? t1 : t0;
            if (gi < gj) sTA += th * atv[r];
        }
    }
    block_reduce_store(sSP, sTA, tid, NOFF + I, wSP, wTA);
}

// ---------- off-diagonal tiles (I<J), 2016 blocks ----------
__global__ void __launch_bounds__(256, 2)
k_pairs_off(const float* __restrict__ X, const float* __restrict__ A) {
    __shared__ float Xt[KK][128], Yt[KK][128], bI[128], bJ[128];
    __shared__ float wSP[8], wTA[8];

    int t = blockIdx.x;
    int I = 0;
    { int rem = t, rl = NT - 1; while (rem >= rl) { rem -= rl; rl--; I++; } t = rem; }
    int J = I + 1 + t;
    int iBase = I * 128, jBase = J * 128;
    int tid = threadIdx.x;

    TileCtx ctx;
    tile_theta(ctx, X, iBase, jBase, tid, Xt, Yt, bI, bJ);
    int tx = ctx.tx, ty = ctx.ty;

    float sSP = 0.f, sTA = 0.f;
    u64 sTA2; PK2(sTA2, 0.f, 0.f);

#pragma unroll
    for (int r = 0; r < 8; r++) {
        int gi = iBase + ty*8 + r;
        float4 a0 = __ldcs((const float4*)&A[gi*NN + jBase + tx*4]);
        float4 a1 = __ldcs((const float4*)&A[gi*NN + jBase + 64 + tx*4]);
        u64 a2[4];
        PK2(a2[0], a0.x, a0.y); PK2(a2[1], a0.z, a0.w);
        PK2(a2[2], a1.x, a1.y); PK2(a2[3], a1.z, a1.w);
#pragma unroll
        for (int cp = 0; cp < 4; cp++) {
            float t0, t1;
            UPK2(t0, t1, ctx.acc2[r][cp]);
            sSP += softplusf(t0) + softplusf(t1);
            FMA2(sTA2, ctx.acc2[r][cp], a2[cp], sTA2);
        }
    }
    // transposed A block
#pragma unroll
    for (int c = 0; c < 8; c++) {
        int gj = jBase + ((c < 4) ? (tx*4 + c) : (64 + tx*4 + (c - 4)));
        float4 b0 = __ldcs((const float4*)&A[gj*NN + iBase + ty*8]);
        float4 b1 = __ldcs((const float4*)&A[gj*NN + iBase + ty*8 + 4]);
        float atv[8] = {b0.x, b0.y, b0.z, b0.w, b1.x, b1.y, b1.z, b1.w};
        int cp = c >> 1;
#pragma unroll
        for (int r = 0; r < 8; r++) {
            float t0, t1;
            UPK2(t0, t1, ctx.acc2[r][cp]);
            sTA += ((c & 1) ? t1 : t0) * atv[r];
        }
    }
    sSP *= 2.f;
    {
        float t0, t1;
        UPK2(t0, t1, sTA2);
        sTA += t0 + t1;
    }
    block_reduce_store(sSP, sTA, tid, blockIdx.x, wSP, wTA);
}

// ---------- deterministic final reduction ----------
__global__ void k_final(float* __restrict__ out) {
    __shared__ double rSP[256], rTA[256];
    int t = threadIdx.x;
    double s1 = 0.0, s2 = 0.0;
    for (int i = t; i < NTILES; i += 256) { s1 += d_partSP[i]; s2 += d_partTA[i]; }
    rSP[t] = s1; rTA[t] = s2; __syncthreads();
    for (int s = 128; s > 0; s >>= 1) {
        if (t < s) { rSP[t] += rSP[t+s]; rTA[t] += rTA[t+s]; }
        __syncthreads();
    }
    if (t == 0) out[0] = (float)(0.5 * rTA[0] - 0.5 * rSP[0]);
}

extern "C" void kernel_launch(void* const* d_in, const int* in_sizes, int n_in,
                              void* d_out, int out_size) {
    const float* A    = (const float*)d_in[0];
    const float* beta = (const float*)d_in[1];
    const float* a    = (const float*)d_in[2];
    const float* X    = (const float*)d_in[3];
    const float* C    = (const float*)d_in[4];
    float* out = (float*)d_out;

    k_prep<<<64, 256>>>(X, C);          // 1
    k_wred<<<1, 256>>>();               // 2
    k_M<<<1, 256>>>();                  // 3
    k_ya<<<NN/32, 128>>>(X, beta, a);   // 4
    k_pairs_diag<<<NT, 256>>>(X, A);    // 5
    k_pairs_off<<<NOFF, 256>>>(X, A);   // 6  <- ncu -s 5 -c 1 captures this
    k_final<<<1, 256>>>(out);           // 7
}